// round 7
// baseline (speedup 1.0000x reference)
#include <cuda_runtime.h>
#include <cstdint>
#include <math.h>

#define SEQ   128
#define BATCH 32
#define EDIM  300
#define HID   200
#define NTAG  17
#define ROWS  (SEQ*BATCH)   // 4096
#define GN    1600          // 2 dirs * 4 gates * 200
#define NCD   50            // CTAs in recurrent kernel (each handles BOTH dirs)
#define LTHREADS 320        // 4 rowgroups x 8 batchgroups x 10 k-slices
#define FSTRIDE 64          // flag spread: 64 words = 256B

// dynamic smem layout (floats)
#define U_STRIDE 202                    // padded row stride (bank spread for 4-row loads)
#define OFF_U    0                      // 2 * 16 * 202 = 6464
#define OFF_H    6464                   // swizzled h, HWORDS
#define HWORDS   6688
#define OFF_PART 13152                  // 10 * 576 = 5760
#define SMEM_FLOATS 18912
#define SMEM_BYTES  (SMEM_FLOATS*4)     // 75648

typedef unsigned long long ull;

#define FFMA2(acc, a, b) asm("fma.rn.f32x2 %0, %1, %2, %3;" : "=l"(acc) : "l"(a), "l"(b), "l"(acc))
#define SPLAT2(dst, f)   asm("mov.b64 %0, {%1, %1};" : "=l"(dst) : "r"(__float_as_uint(f)))

// ---------------- scratch (static device allocations) ----------------
__device__ float d_X0[ROWS*EDIM];
__device__ float d_G0[ROWS*GN];
__device__ float d_G1[ROWS*GN];
__device__ float d_H0r[ROWS*400];        // row-major [t*32+b][dir*200+j]
__device__ float d_H1r[ROWS*400];
__device__ float d_H0t[SEQ*2*HID*BATCH]; // transposed [t][dir][j][b]
__device__ float d_H1t[SEQ*2*HID*BATCH];
__device__ unsigned g_flags[4][NCD * FSTRIDE];   // [layer*2 + dir]

__device__ __forceinline__ float fsig(float x) {
    return __fdividef(1.0f, 1.0f + __expf(-x));
}
__device__ __forceinline__ float ftanh(float x) {
    return 1.0f - __fdividef(2.0f, __expf(2.0f * x) + 1.0f);
}
// swizzled float base of h row b: 4-row LDS.64 groups hit distinct 8B banks
__device__ __forceinline__ int hbase(int b) { return b * 208 + ((b >> 1) << 1); }

// ---------------- flag reset ----------------
__global__ void reset_cnt_kernel() {
    int n = 4 * NCD * FSTRIDE;
    unsigned* p = &g_flags[0][0];
    for (int i = threadIdx.x + blockIdx.x * blockDim.x; i < n; i += blockDim.x * gridDim.x)
        p[i] = 0u;
}

// ---------------- embedding gather ----------------
__global__ void gather_kernel(const int* __restrict__ words,
                              const float* __restrict__ emb) {
    int idx = blockIdx.x * blockDim.x + threadIdx.x;
    if (idx >= ROWS * EDIM) return;
    int row = idx / EDIM;
    int e   = idx - row * EDIM;
    int t = row >> 5;
    int b = row & 31;
    int w = words[b * SEQ + t];
    d_X0[idx] = emb[(size_t)w * EDIM + e];
}

// ---------------- fp32 GEMM with FFMA2: C = A @ W^T + bias ----------------
__global__ __launch_bounds__(256)
void sgemm_bias_kernel(const float* __restrict__ A, const float* __restrict__ W,
                       const float* __restrict__ bias, float* __restrict__ C,
                       int M, int N, int K) {
    __shared__ __align__(16) float As[8][128];
    __shared__ __align__(16) float Bs[8][64];

    int tid = threadIdx.x;
    int tx = tid & 15;
    int ty = tid >> 4;
    int m0 = blockIdx.y * 128;
    int n0 = blockIdx.x * 64;

    ull acc2[4][4];
#pragma unroll
    for (int p = 0; p < 4; p++)
#pragma unroll
        for (int j = 0; j < 4; j++) acc2[p][j] = 0ull;

    int arow = tid >> 1;
    int ak   = (tid & 1) * 4;
    int brow = tid >> 2;
    int bk   = (tid & 3) * 2;

    const float* Arow = A + (size_t)(m0 + arow) * K;
    const float* Wrow = W + (size_t)(n0 + brow) * K;

    for (int k0 = 0; k0 < K; k0 += 8) {
#pragma unroll
        for (int j = 0; j < 4; j++) {
            int k = k0 + ak + j;
            As[ak + j][arow] = (k < K) ? Arow[k] : 0.f;
        }
#pragma unroll
        for (int j = 0; j < 2; j++) {
            int k = k0 + bk + j;
            Bs[bk + j][brow] = (k < K) ? Wrow[k] : 0.f;
        }
        __syncthreads();
#pragma unroll
        for (int kk = 0; kk < 8; kk++) {
            const ulonglong2* ap = (const ulonglong2*)&As[kk][ty * 8];
            ulonglong2 apA = ap[0], apB = ap[1];
            ull am2[4] = {apA.x, apA.y, apB.x, apB.y};
            float4 bv = *(const float4*)&Bs[kk][tx * 4];
            ull bs2[4];
            SPLAT2(bs2[0], bv.x); SPLAT2(bs2[1], bv.y);
            SPLAT2(bs2[2], bv.z); SPLAT2(bs2[3], bv.w);
#pragma unroll
            for (int p = 0; p < 4; p++)
#pragma unroll
                for (int j = 0; j < 4; j++)
                    FFMA2(acc2[p][j], am2[p], bs2[j]);
        }
        __syncthreads();
    }

    float4 bb = *(const float4*)&bias[n0 + tx * 4];
    float bn[4] = {bb.x, bb.y, bb.z, bb.w};
#pragma unroll
    for (int i = 0; i < 8; i++) {
        int m = m0 + ty * 8 + i;
        float4 v;
        float2 f0 = *((float2*)&acc2[i >> 1][0]);
        float2 f1 = *((float2*)&acc2[i >> 1][1]);
        float2 f2 = *((float2*)&acc2[i >> 1][2]);
        float2 f3 = *((float2*)&acc2[i >> 1][3]);
        v.x = ((i & 1) ? f0.y : f0.x) + bn[0];
        v.y = ((i & 1) ? f1.y : f1.x) + bn[1];
        v.z = ((i & 1) ? f2.y : f2.x) + bn[2];
        v.w = ((i & 1) ? f3.y : f3.x) + bn[3];
        *(float4*)&C[(size_t)m * N + n0 + tx * 4] = v;
    }
}

// ---------------- persistent dual-direction LSTM layer ----------------
// CTA cb: owns h cols j0..j0+3 for BOTH directions (fwd phase then bwd phase
// per step; each direction's barrier latency hides under the other's compute).
__global__ __launch_bounds__(LTHREADS, 1)
void lstm_layer_kernel(const float* __restrict__ G, const float* __restrict__ Whh,
                       float* __restrict__ Ht, float* __restrict__ Hr,
                       unsigned* flags) {
    extern __shared__ __align__(16) float smem[];
    float* sh_U    = smem + OFF_U;     // [2][16][U_STRIDE]
    float* sh_h    = smem + OFF_H;     // swizzled [b][k]
    float* sh_part = smem + OFF_PART;  // [10][16*36]

    int tid = threadIdx.x;
    int cb  = blockIdx.x;
    int j0  = cb * 4;

    // preload U rows for both dirs: local row r = g*4+q -> Whh[d][g*200+j0+q][:]
    for (int idx = tid; idx < 2 * 16 * 200; idx += LTHREADS) {
        int d = idx / 3200;
        int rem = idx - d * 3200;
        int r = rem / 200, k = rem - r * 200;
        int g = r >> 2, q = r & 3;
        sh_U[d * (16 * U_STRIDE) + r * U_STRIDE + k] =
            Whh[(size_t)d * 800 * 200 + (size_t)(g * 200 + j0 + q) * 200 + k];
    }
    for (int idx = tid; idx < HWORDS; idx += LTHREADS) sh_h[idx] = 0.f;
    __syncthreads();

    // matvec decode: kq = warp id (0..9), rg = (lane>>3)&3, bg = lane&7
    int lane = tid & 31;
    int kq = tid >> 5;
    int rg = (lane >> 3) & 3;
    int bg = lane & 7;
    int rbase = 4 * rg;
    int bb = 4 * bg;

    const ull* pu[4];
    const ull* ph[4];
#pragma unroll
    for (int i = 0; i < 4; i++)
        ph[i] = (const ull*)(sh_h + hbase(bb + i)) + kq * 10;

    // epilogue identity (tid < 128): col q = eq, batch eb
    int eq = tid >> 5;
    int eb = tid & 31;
    float creg[2] = {0.f, 0.f};
    const float* Gb[2];
    Gb[0] = G + 0 * 800 + (j0 + eq) + (size_t)eb * GN;
    Gb[1] = G + 1 * 800 + (j0 + eq) + (size_t)eb * GN;

    // poll pointers: every warp polls (lane<25 handles 2 flags)
    bool pmine = lane < 25;
    int pi0 = pmine ? lane : 0;
    int pi1 = pmine ? (lane + 25) : 0;

    // G prefetch for step 0, both dirs
    float gc[2][4];
    if (tid < 128) {
#pragma unroll
        for (int d = 0; d < 2; d++) {
            int t0 = d ? (SEQ - 1) : 0;
            const float* Gp = Gb[d] + (size_t)t0 * (32 * GN);
            gc[d][0] = __ldg(Gp);       gc[d][1] = __ldg(Gp + 200);
            gc[d][2] = __ldg(Gp + 400); gc[d][3] = __ldg(Gp + 600);
        }
    } else {
#pragma unroll
        for (int d = 0; d < 2; d++)
#pragma unroll
            for (int i = 0; i < 4; i++) gc[d][i] = 0.f;
    }

    for (int step = 0; step < SEQ; step++) {
#pragma unroll
        for (int d = 0; d < 2; d++) {
            int t = d ? (SEQ - 1 - step) : step;
            unsigned* fl = flags + d * (NCD * FSTRIDE);

            if (step > 0) {
                // per-warp poll: this dir's step-1 h published by all CTAs
                unsigned target = (unsigned)step;
                const unsigned* q0 = fl + pi0 * FSTRIDE;
                const unsigned* q1 = fl + pi1 * FSTRIDE;
                bool done;
                do {
                    unsigned v0 = target, v1 = target;
                    if (pmine) {
                        asm volatile("ld.relaxed.gpu.global.u32 %0, [%1];"
                                     : "=r"(v0) : "l"(q0) : "memory");
                        asm volatile("ld.relaxed.gpu.global.u32 %0, [%1];"
                                     : "=r"(v1) : "l"(q1) : "memory");
                    }
                    done = (v0 >= target) && (v1 >= target);
                } while (__ballot_sync(0xffffffffu, done) != 0xffffffffu);
                asm volatile("fence.acq_rel.gpu;" ::: "memory");

                // load h_{prev} (transposed [j][b]) into swizzled smem [b][k]
                int tp = d ? (t + 1) : (t - 1);
                const float* Hp = Ht + (size_t)(tp * 2 + d) * (HID * BATCH);
                for (int idx = tid; idx < 1600; idx += LTHREADS) {
                    int j  = idx >> 3;
                    int b4 = (idx & 7) * 4;
                    float4 v = __ldcg((const float4*)(Hp + j * 32 + b4));
                    sh_h[hbase(b4 + 0) + j] = v.x;
                    sh_h[hbase(b4 + 1) + j] = v.y;
                    sh_h[hbase(b4 + 2) + j] = v.z;
                    sh_h[hbase(b4 + 3) + j] = v.w;
                }
            }
            __syncthreads();   // h ready (or zeros at step 0)

            // matvec: 4 rows x 4 batches, k-slice of 10 u64
            const float* Ub = sh_U + d * (16 * U_STRIDE);
#pragma unroll
            for (int i = 0; i < 4; i++)
                pu[i] = (const ull*)(Ub + (rbase + i) * U_STRIDE) + kq * 10;

            ull acc[4][4];
#pragma unroll
            for (int i = 0; i < 4; i++)
#pragma unroll
                for (int j = 0; j < 4; j++) acc[i][j] = 0ull;

#pragma unroll
            for (int kk = 0; kk < 10; kk++) {
                ull u0 = pu[0][kk], u1 = pu[1][kk], u2 = pu[2][kk], u3 = pu[3][kk];
                ull h0 = ph[0][kk], h1 = ph[1][kk], h2 = ph[2][kk], h3 = ph[3][kk];
                FFMA2(acc[0][0], u0, h0); FFMA2(acc[0][1], u0, h1);
                FFMA2(acc[0][2], u0, h2); FFMA2(acc[0][3], u0, h3);
                FFMA2(acc[1][0], u1, h0); FFMA2(acc[1][1], u1, h1);
                FFMA2(acc[1][2], u1, h2); FFMA2(acc[1][3], u1, h3);
                FFMA2(acc[2][0], u2, h0); FFMA2(acc[2][1], u2, h1);
                FFMA2(acc[2][2], u2, h2); FFMA2(acc[2][3], u2, h3);
                FFMA2(acc[3][0], u3, h0); FFMA2(acc[3][1], u3, h1);
                FFMA2(acc[3][2], u3, h2); FFMA2(acc[3][3], u3, h3);
            }
#pragma unroll
            for (int i = 0; i < 4; i++) {
                float4 v;
                float2 f;
                f = *(float2*)&acc[i][0]; v.x = f.x + f.y;
                f = *(float2*)&acc[i][1]; v.y = f.x + f.y;
                f = *(float2*)&acc[i][2]; v.z = f.x + f.y;
                f = *(float2*)&acc[i][3]; v.w = f.x + f.y;
                *(float4*)&sh_part[kq * 576 + (rbase + i) * 36 + bb] = v;
            }
            __syncthreads();   // partials ready

            // epilogue
            float hn = 0.f;
            if (tid < 128) {
                float y[4];
#pragma unroll
                for (int g = 0; g < 4; g++) {
                    int r = 4 * g + eq;
                    float s = 0.f;
#pragma unroll
                    for (int k2 = 0; k2 < 10; k2++)
                        s += sh_part[k2 * 576 + r * 36 + eb];
                    y[g] = s;
                }
                float yi = y[0] + gc[d][0];
                float yf = y[1] + gc[d][1];
                float yg = y[2] + gc[d][2];
                float yo = y[3] + gc[d][3];
                float c = fsig(yf) * creg[d] + fsig(yi) * ftanh(yg);
                hn = fsig(yo) * ftanh(c);
                creg[d] = c;
                Ht[(size_t)(t * 2 + d) * (HID * BATCH) + (j0 + eq) * 32 + eb] = hn;
                // prefetch this dir's G for step+1
                if (step + 1 < SEQ) {
                    int tn = d ? (t - 1) : (t + 1);
                    const float* Gp = Gb[d] + (size_t)tn * (32 * GN);
                    gc[d][0] = __ldg(Gp);       gc[d][1] = __ldg(Gp + 200);
                    gc[d][2] = __ldg(Gp + 400); gc[d][3] = __ldg(Gp + 600);
                }
            }
            __syncthreads();   // Ht stores done CTA-wide before release

            if (step < SEQ - 1 && tid == 0) {
                unsigned* myflag = fl + cb * FSTRIDE;
                asm volatile("st.release.gpu.global.u32 [%0], %1;"
                             :: "l"(myflag), "r"((unsigned)(step + 1)) : "memory");
            }
            // row-major copy off the critical path
            if (tid < 128)
                Hr[(size_t)(t * 32 + eb) * 400 + d * 200 + (j0 + eq)] = hn;
        }
    }
}

// ---------------- output head ----------------
__global__ void out_kernel(const float* __restrict__ ow, const float* __restrict__ ob,
                           float* __restrict__ out) {
    int row  = blockIdx.x;           // = s*32 + b
    int warp = threadIdx.x >> 5;     // 0..16 = tag
    int lane = threadIdx.x & 31;
    const float* h    = d_H1r + (size_t)row * 400;
    const float* wrow = ow + warp * 400;
    float sum = 0.f;
#pragma unroll
    for (int k = lane; k < 400; k += 32) sum = fmaf(h[k], wrow[k], sum);
#pragma unroll
    for (int o = 16; o; o >>= 1) sum += __shfl_down_sync(0xffffffffu, sum, o);
    if (lane == 0) {
        int s = row >> 5, b = row & 31;
        out[((size_t)b * SEQ + s) * NTAG + warp] = fsig(sum + ob[warp]);
    }
}

// ---------------- launch ----------------
extern "C" void kernel_launch(void* const* d_in, const int* in_sizes, int n_in,
                              void* d_out, int out_size) {
    const int*   words = (const int*)  d_in[0];
    const float* emb   = (const float*)d_in[3];
    const float* Wih0  = (const float*)d_in[7];
    const float* Whh0  = (const float*)d_in[8];
    const float* b0    = (const float*)d_in[9];
    const float* Wih1  = (const float*)d_in[10];
    const float* Whh1  = (const float*)d_in[11];
    const float* b1    = (const float*)d_in[12];
    const float* ow    = (const float*)d_in[13];
    const float* ob    = (const float*)d_in[14];
    float* out = (float*)d_out;

    float *pX0, *pG0, *pG1, *pH0r, *pH1r, *pH0t, *pH1t;
    unsigned* pflags;
    cudaGetSymbolAddress((void**)&pX0, d_X0);
    cudaGetSymbolAddress((void**)&pG0, d_G0);
    cudaGetSymbolAddress((void**)&pG1, d_G1);
    cudaGetSymbolAddress((void**)&pH0r, d_H0r);
    cudaGetSymbolAddress((void**)&pH1r, d_H1r);
    cudaGetSymbolAddress((void**)&pH0t, d_H0t);
    cudaGetSymbolAddress((void**)&pH1t, d_H1t);
    cudaGetSymbolAddress((void**)&pflags, g_flags);

    static int smem_set = 0;
    if (!smem_set) {
        cudaFuncSetAttribute(lstm_layer_kernel,
                             cudaFuncAttributeMaxDynamicSharedMemorySize, SMEM_BYTES);
        smem_set = 1;
    }

    reset_cnt_kernel<<<13, 512>>>();

    gather_kernel<<<(ROWS * EDIM + 255) / 256, 256>>>(words, emb);

    dim3 gdim0(GN / 64, ROWS / 128);
    sgemm_bias_kernel<<<gdim0, 256>>>(pX0, Wih0, b0, pG0, ROWS, GN, EDIM);

    lstm_layer_kernel<<<NCD, LTHREADS, SMEM_BYTES>>>(pG0, Whh0, pH0t, pH0r,
                                                     pflags + 0 * NCD * FSTRIDE);

    sgemm_bias_kernel<<<gdim0, 256>>>(pH0r, Wih1, b1, pG1, ROWS, GN, 400);

    lstm_layer_kernel<<<NCD, LTHREADS, SMEM_BYTES>>>(pG1, Whh1, pH1t, pH1r,
                                                     pflags + 2 * NCD * FSTRIDE);

    out_kernel<<<ROWS, NTAG * 32>>>(ow, ob, out);
}

// round 8
// speedup vs baseline: 1.3137x; 1.3137x over previous
#include <cuda_runtime.h>
#include <cstdint>
#include <math.h>

#define SEQ   128
#define BATCH 32
#define EDIM  300
#define HID   200
#define NTAG  17
#define ROWS  (SEQ*BATCH)   // 4096
#define GN    1600          // 2 dirs * 4 gates * 200
#define NCD   50            // CTAs in recurrent kernel (each: both dirs, 4 cols)
#define LTHREADS 512        // 256 per direction half
#define CSTRIDE 64          // counter spread (words)

// dynamic smem layout (floats)
#define OFF_U  0            // [2][16*200] = 6400
#define OFF_H  6400         // [2][HWORDS]
#define HWORDS 6688
#define OFF_P  19776        // [2][2*528] = 2112
#define SMEM_FLOATS 21888
#define SMEM_BYTES  (SMEM_FLOATS*4)   // 87552

typedef unsigned long long ull;

#define FFMA2(acc, a, b) asm("fma.rn.f32x2 %0, %1, %2, %3;" : "=l"(acc) : "l"(a), "l"(b), "l"(acc))
#define SPLAT2(dst, f)   asm("mov.b64 %0, {%1, %1};" : "=l"(dst) : "r"(__float_as_uint(f)))
#define NBAR(id) asm volatile("bar.sync %0, %1;" :: "r"(id), "r"(256) : "memory")

// ---------------- scratch (static device allocations) ----------------
__device__ float d_X0[ROWS*EDIM];
__device__ float d_G0[ROWS*GN];
__device__ float d_G1[ROWS*GN];
__device__ float d_H0r[ROWS*400];        // row-major [t*32+b][dir*200+j]
__device__ float d_H1r[ROWS*400];
__device__ float d_H0t[SEQ*2*HID*BATCH]; // transposed [t][dir][j][b]
__device__ float d_H1t[SEQ*2*HID*BATCH];
__device__ unsigned g_cnt[4 * CSTRIDE];  // counters: (layer*2 + dir) * CSTRIDE

__device__ __forceinline__ float fsig(float x) {
    return __fdividef(1.0f, 1.0f + __expf(-x));
}
__device__ __forceinline__ float ftanh(float x) {
    return 1.0f - __fdividef(2.0f, __expf(2.0f * x) + 1.0f);
}
// swizzled float base of h row b (16 distinct 8B banks across even/odd rows)
__device__ __forceinline__ int hbase(int b) { return b * 208 + ((b >> 1) << 1); }

// ---------------- counter reset ----------------
__global__ void reset_cnt_kernel() {
    int i = threadIdx.x + blockIdx.x * blockDim.x;
    if (i < 4 * CSTRIDE) g_cnt[i] = 0u;
}

// ---------------- embedding gather ----------------
__global__ void gather_kernel(const int* __restrict__ words,
                              const float* __restrict__ emb) {
    int idx = blockIdx.x * blockDim.x + threadIdx.x;
    if (idx >= ROWS * EDIM) return;
    int row = idx / EDIM;
    int e   = idx - row * EDIM;
    int t = row >> 5;
    int b = row & 31;
    int w = words[b * SEQ + t];
    d_X0[idx] = emb[(size_t)w * EDIM + e];
}

// ---------------- fp32 GEMM with FFMA2: C = A @ W^T + bias ----------------
__global__ __launch_bounds__(256)
void sgemm_bias_kernel(const float* __restrict__ A, const float* __restrict__ W,
                       const float* __restrict__ bias, float* __restrict__ C,
                       int M, int N, int K) {
    __shared__ __align__(16) float As[8][128];
    __shared__ __align__(16) float Bs[8][64];

    int tid = threadIdx.x;
    int tx = tid & 15;
    int ty = tid >> 4;
    int m0 = blockIdx.y * 128;
    int n0 = blockIdx.x * 64;

    ull acc2[4][4];
#pragma unroll
    for (int p = 0; p < 4; p++)
#pragma unroll
        for (int j = 0; j < 4; j++) acc2[p][j] = 0ull;

    int arow = tid >> 1;
    int ak   = (tid & 1) * 4;
    int brow = tid >> 2;
    int bk   = (tid & 3) * 2;

    const float* Arow = A + (size_t)(m0 + arow) * K;
    const float* Wrow = W + (size_t)(n0 + brow) * K;

    for (int k0 = 0; k0 < K; k0 += 8) {
#pragma unroll
        for (int j = 0; j < 4; j++) {
            int k = k0 + ak + j;
            As[ak + j][arow] = (k < K) ? Arow[k] : 0.f;
        }
#pragma unroll
        for (int j = 0; j < 2; j++) {
            int k = k0 + bk + j;
            Bs[bk + j][brow] = (k < K) ? Wrow[k] : 0.f;
        }
        __syncthreads();
#pragma unroll
        for (int kk = 0; kk < 8; kk++) {
            const ulonglong2* ap = (const ulonglong2*)&As[kk][ty * 8];
            ulonglong2 apA = ap[0], apB = ap[1];
            ull am2[4] = {apA.x, apA.y, apB.x, apB.y};
            float4 bv = *(const float4*)&Bs[kk][tx * 4];
            ull bs2[4];
            SPLAT2(bs2[0], bv.x); SPLAT2(bs2[1], bv.y);
            SPLAT2(bs2[2], bv.z); SPLAT2(bs2[3], bv.w);
#pragma unroll
            for (int p = 0; p < 4; p++)
#pragma unroll
                for (int j = 0; j < 4; j++)
                    FFMA2(acc2[p][j], am2[p], bs2[j]);
        }
        __syncthreads();
    }

    float4 bb = *(const float4*)&bias[n0 + tx * 4];
    float bn[4] = {bb.x, bb.y, bb.z, bb.w};
#pragma unroll
    for (int i = 0; i < 8; i++) {
        int m = m0 + ty * 8 + i;
        float4 v;
        float2 f0 = *((float2*)&acc2[i >> 1][0]);
        float2 f1 = *((float2*)&acc2[i >> 1][1]);
        float2 f2 = *((float2*)&acc2[i >> 1][2]);
        float2 f3 = *((float2*)&acc2[i >> 1][3]);
        v.x = ((i & 1) ? f0.y : f0.x) + bn[0];
        v.y = ((i & 1) ? f1.y : f1.x) + bn[1];
        v.z = ((i & 1) ? f2.y : f2.x) + bn[2];
        v.w = ((i & 1) ? f3.y : f3.x) + bn[3];
        *(float4*)&C[(size_t)m * N + n0 + tx * 4] = v;
    }
}

// ---------------- persistent bidirectional LSTM layer ----------------
// 50 CTAs; CTA cb owns h cols j0..j0+3 for BOTH directions as two INDEPENDENT
// 256-thread halves (d = tid>>8). Halves sync only via named barriers 1+d, so
// one direction's grid-barrier wait overlaps the other direction's compute on
// the same SM.
__global__ __launch_bounds__(LTHREADS, 1)
void lstm_layer_kernel(const float* __restrict__ G, const float* __restrict__ Whh,
                       float* __restrict__ Ht, float* __restrict__ Hr,
                       unsigned* cnt) {
    extern __shared__ __align__(16) float smem[];

    int tid = threadIdx.x;
    int cb  = blockIdx.x;
    int j0  = cb * 4;

    // ---- cooperative init (all 512 threads), then one full sync ----
    for (int idx = tid; idx < 2 * 16 * 200; idx += LTHREADS) {
        int d2 = idx / 3200;
        int rem = idx - d2 * 3200;
        int r = rem / 200, k = rem - r * 200;
        int g = r >> 2, q = r & 3;
        smem[OFF_U + d2 * 3200 + r * 200 + k] =
            Whh[(size_t)d2 * 800 * 200 + (size_t)(g * 200 + j0 + q) * 200 + k];
    }
    for (int idx = tid; idx < 2 * HWORDS; idx += LTHREADS)
        smem[OFF_H + idx] = 0.f;
    __syncthreads();

    // ---- per-half identity ----
    int d  = tid >> 8;          // direction
    int ht = tid & 255;         // thread id within half
    int barid = 1 + d;
    float* Ud = smem + OFF_U + d * 3200;
    float* hd = smem + OFF_H + d * HWORDS;
    float* Pd = smem + OFF_P + d * 1056;
    unsigned* mycnt = cnt + d * CSTRIDE;

    // matvec decode: 2r x 2b tile, k-split 2 (50 u64 each)
    int bp = ht & 15;
    int rp = (ht >> 4) & 7;
    int kq = ht >> 7;
    int b0 = 2 * bp, b1 = b0 + 1;
    int r0 = 2 * rp, r1 = r0 + 1;
    const ull* pu0 = (const ull*)(Ud + r0 * 200) + kq * 50;
    const ull* pu1 = (const ull*)(Ud + r1 * 200) + kq * 50;
    const ull* ph0 = (const ull*)(hd + hbase(b0)) + kq * 50;
    const ull* ph1 = (const ull*)(hd + hbase(b1)) + kq * 50;

    // epilogue identity (ht < 128): col eq, batch eb
    int eq = ht >> 5;
    int eb = ht & 31;
    float creg = 0.f;
    const float* Gbase = G + d * 800 + (j0 + eq) + (size_t)eb * GN;

    // G prefetch for step 0
    float gc[4] = {0.f, 0.f, 0.f, 0.f};
    if (ht < 128) {
        int t0 = d ? (SEQ - 1) : 0;
        const float* Gp = Gbase + (size_t)t0 * (32 * GN);
        gc[0] = __ldg(Gp);       gc[1] = __ldg(Gp + 200);
        gc[2] = __ldg(Gp + 400); gc[3] = __ldg(Gp + 600);
    }

    bool pollwarp = (ht >> 5) == 0;   // warp 0 of this half

    for (int step = 0; step < SEQ; step++) {
        int t = d ? (SEQ - 1 - step) : step;

        // ---- phase 1: load h_{t-1} ([j][b] transposed -> swizzled [b][k]) ----
        if (step > 0) {
            int tp = d ? (t + 1) : (t - 1);
            const float* Hp = Ht + (size_t)(tp * 2 + d) * (HID * BATCH);
            for (int idx = ht; idx < 1600; idx += 256) {
                int j  = idx >> 3;
                int b4 = (idx & 7) * 4;
                float4 v = __ldcg((const float4*)(Hp + j * 32 + b4));
                hd[hbase(b4 + 0) + j] = v.x;
                hd[hbase(b4 + 1) + j] = v.y;
                hd[hbase(b4 + 2) + j] = v.z;
                hd[hbase(b4 + 3) + j] = v.w;
            }
        }
        NBAR(barid);

        // ---- phase 2: matvec 2r x 2b over 50 u64 ----
        ull a00 = 0ull, a01 = 0ull, a10 = 0ull, a11 = 0ull;
#pragma unroll 10
        for (int kk = 0; kk < 50; kk++) {
            ull h0v = ph0[kk];
            ull h1v = ph1[kk];
            ull u0v = pu0[kk];
            ull u1v = pu1[kk];
            FFMA2(a00, u0v, h0v);
            FFMA2(a01, u0v, h1v);
            FFMA2(a10, u1v, h0v);
            FFMA2(a11, u1v, h1v);
        }
        {
            float2 f;
            float* P = Pd + kq * 528;
            f = *(float2*)&a00; P[r0 * 33 + b0] = f.x + f.y;
            f = *(float2*)&a01; P[r0 * 33 + b1] = f.x + f.y;
            f = *(float2*)&a10; P[r1 * 33 + b0] = f.x + f.y;
            f = *(float2*)&a11; P[r1 * 33 + b1] = f.x + f.y;
        }
        NBAR(barid);

        // ---- phase 3: epilogue ----
        if (ht < 128) {
            float y[4];
#pragma unroll
            for (int g = 0; g < 4; g++) {
                int r = 4 * g + eq;
                y[g] = Pd[r * 33 + eb] + Pd[528 + r * 33 + eb];
            }
            float yi = y[0] + gc[0];
            float yf = y[1] + gc[1];
            float yg = y[2] + gc[2];
            float yo = y[3] + gc[3];
            float c = fsig(yf) * creg + fsig(yi) * ftanh(yg);
            float hn = fsig(yo) * ftanh(c);
            creg = c;
            Ht[(size_t)(t * 2 + d) * (HID * BATCH) + (j0 + eq) * 32 + eb] = hn;
            Hr[(size_t)(t * 32 + eb) * 400 + d * 200 + (j0 + eq)] = hn;
            // G prefetch for next step (latency spans release+poll+hload)
            if (step + 1 < SEQ) {
                int tn = d ? (t - 1) : (t + 1);
                const float* Gp = Gbase + (size_t)tn * (32 * GN);
                gc[0] = __ldg(Gp);       gc[1] = __ldg(Gp + 200);
                gc[2] = __ldg(Gp + 400); gc[3] = __ldg(Gp + 600);
            }
        }
        NBAR(barid);   // Ht stores ordered before release (intra-half HB)

        // ---- phase 4: grid barrier for this direction ----
        if (step < SEQ - 1) {
            if (pollwarp) {
                if (ht == 0) {
                    asm volatile("red.release.gpu.global.add.u32 [%0], 1;"
                                 :: "l"(mycnt) : "memory");
                }
                unsigned target = (unsigned)NCD * (unsigned)(step + 1);
                unsigned v;
                do {
                    asm volatile("ld.global.acquire.gpu.u32 %0, [%1];"
                                 : "=r"(v) : "l"(mycnt) : "memory");
                } while (v < target);
            }
            NBAR(barid);
        }
    }
}

// ---------------- output head ----------------
__global__ void out_kernel(const float* __restrict__ ow, const float* __restrict__ ob,
                           float* __restrict__ out) {
    int row  = blockIdx.x;           // = s*32 + b
    int warp = threadIdx.x >> 5;     // 0..16 = tag
    int lane = threadIdx.x & 31;
    const float* h    = d_H1r + (size_t)row * 400;
    const float* wrow = ow + warp * 400;
    float sum = 0.f;
#pragma unroll
    for (int k = lane; k < 400; k += 32) sum = fmaf(h[k], wrow[k], sum);
#pragma unroll
    for (int o = 16; o; o >>= 1) sum += __shfl_down_sync(0xffffffffu, sum, o);
    if (lane == 0) {
        int s = row >> 5, b = row & 31;
        out[((size_t)b * SEQ + s) * NTAG + warp] = fsig(sum + ob[warp]);
    }
}

// ---------------- launch ----------------
extern "C" void kernel_launch(void* const* d_in, const int* in_sizes, int n_in,
                              void* d_out, int out_size) {
    const int*   words = (const int*)  d_in[0];
    const float* emb   = (const float*)d_in[3];
    const float* Wih0  = (const float*)d_in[7];
    const float* Whh0  = (const float*)d_in[8];
    const float* b0    = (const float*)d_in[9];
    const float* Wih1  = (const float*)d_in[10];
    const float* Whh1  = (const float*)d_in[11];
    const float* b1    = (const float*)d_in[12];
    const float* ow    = (const float*)d_in[13];
    const float* ob    = (const float*)d_in[14];
    float* out = (float*)d_out;

    float *pX0, *pG0, *pG1, *pH0r, *pH1r, *pH0t, *pH1t;
    unsigned* pcnt;
    cudaGetSymbolAddress((void**)&pX0, d_X0);
    cudaGetSymbolAddress((void**)&pG0, d_G0);
    cudaGetSymbolAddress((void**)&pG1, d_G1);
    cudaGetSymbolAddress((void**)&pH0r, d_H0r);
    cudaGetSymbolAddress((void**)&pH1r, d_H1r);
    cudaGetSymbolAddress((void**)&pH0t, d_H0t);
    cudaGetSymbolAddress((void**)&pH1t, d_H1t);
    cudaGetSymbolAddress((void**)&pcnt, g_cnt);

    static int smem_set = 0;
    if (!smem_set) {
        cudaFuncSetAttribute(lstm_layer_kernel,
                             cudaFuncAttributeMaxDynamicSharedMemorySize, SMEM_BYTES);
        smem_set = 1;
    }

    reset_cnt_kernel<<<1, 4 * CSTRIDE>>>();

    gather_kernel<<<(ROWS * EDIM + 255) / 256, 256>>>(words, emb);

    dim3 gdim0(GN / 64, ROWS / 128);
    sgemm_bias_kernel<<<gdim0, 256>>>(pX0, Wih0, b0, pG0, ROWS, GN, EDIM);

    lstm_layer_kernel<<<NCD, LTHREADS, SMEM_BYTES>>>(pG0, Whh0, pH0t, pH0r,
                                                     pcnt + 0 * CSTRIDE * 2);

    sgemm_bias_kernel<<<gdim0, 256>>>(pH0r, Wih1, b1, pG1, ROWS, GN, 400);

    lstm_layer_kernel<<<NCD, LTHREADS, SMEM_BYTES>>>(pG1, Whh1, pH1t, pH1r,
                                                     pcnt + 1 * CSTRIDE * 2);

    out_kernel<<<ROWS, NTAG * 32>>>(ow, ob, out);
}

// round 11
// speedup vs baseline: 2.2076x; 1.6805x over previous
#include <cuda_runtime.h>
#include <cstdint>
#include <math.h>

#define SEQ   128
#define BATCH 32
#define EDIM  300
#define HID   200
#define NTAG  17
#define ROWS  (SEQ*BATCH)   // 4096
#define GN    1600          // 2 dirs * 4 gates * 200

// ---- LSTM decomposition ----
// 128 CTAs: cid = blockIdx>>3 (dir = cid&1, b8 = cid>>1), rg = blockIdx&7.
// CTA owns gate rows r = g*25+jj -> global (g*200 + rg*25 + jj), g=0..3,
// and batches gb = b8*4..b8*4+3. Barrier group = 8 CTAs sharing (dir,b8).
#define LTHREADS 256
#define CSTRIDE 64                 // counter spread (words)

// dynamic smem (floats)
#define OFF_U  0                   // swizzled U: ubase(r)=r*202+2*(r>>1)
#define U_FLOATS 20304             // max ubase(99)+200 = 20296
#define OFF_H  U_FLOATS            // h[4][202]
#define H_FLOATS 808
#define OFF_P  (OFF_U + U_FLOATS + H_FLOATS)   // partials [4][100*5]
#define P_FLOATS 2004
#define SMEM_FLOATS (OFF_P + P_FLOATS)
#define SMEM_BYTES  (SMEM_FLOATS * 4)          // ~92.5 KB

typedef unsigned long long ull;

#define FFMA2(acc, a, b) asm("fma.rn.f32x2 %0, %1, %2, %3;" : "=l"(acc) : "l"(a), "l"(b), "l"(acc))
#define SPLAT2(dst, f)   asm("mov.b64 %0, {%1, %1};" : "=l"(dst) : "r"(__float_as_uint(f)))

// ---------------- scratch (static device allocations) ----------------
__device__ float d_X0[ROWS*EDIM];
__device__ float d_G0[ROWS*GN];
__device__ float d_G1[ROWS*GN];
__device__ float d_H0r[ROWS*400];        // row-major [t*32+b][dir*200+j]
__device__ float d_H1r[ROWS*400];
__device__ float d_Ht[SEQ*2*8*800];      // exchange [t][dir][b8][j*4+bl]
__device__ unsigned g_cnt[2 * 16 * CSTRIDE];  // per-layer, per-(dir,b8)

__device__ __forceinline__ float fsig(float x) {
    return __fdividef(1.0f, 1.0f + __expf(-x));
}
__device__ __forceinline__ float ftanh(float x) {
    return 1.0f - __fdividef(2.0f, __expf(2.0f * x) + 1.0f);
}
// U row base in u64 units: both rows of a pair cycle all 16 banks over rp
__device__ __forceinline__ int ub64(int r) { return r * 101 + (r >> 1); }

// ---------------- counter reset ----------------
__global__ void reset_cnt_kernel() {
    int n = 2 * 16 * CSTRIDE;
    for (int i = threadIdx.x + blockIdx.x * blockDim.x; i < n; i += blockDim.x * gridDim.x)
        g_cnt[i] = 0u;
}

// ---------------- embedding gather ----------------
__global__ void gather_kernel(const int* __restrict__ words,
                              const float* __restrict__ emb) {
    int idx = blockIdx.x * blockDim.x + threadIdx.x;
    if (idx >= ROWS * EDIM) return;
    int row = idx / EDIM;
    int e   = idx - row * EDIM;
    int t = row >> 5;
    int b = row & 31;
    int w = words[b * SEQ + t];
    d_X0[idx] = emb[(size_t)w * EDIM + e];
}

// ---------------- fp32 GEMM with FFMA2: C = A @ W^T + bias ----------------
__global__ __launch_bounds__(256)
void sgemm_bias_kernel(const float* __restrict__ A, const float* __restrict__ W,
                       const float* __restrict__ bias, float* __restrict__ C,
                       int M, int N, int K) {
    __shared__ __align__(16) float As[8][128];
    __shared__ __align__(16) float Bs[8][64];

    int tid = threadIdx.x;
    int tx = tid & 15;
    int ty = tid >> 4;
    int m0 = blockIdx.y * 128;
    int n0 = blockIdx.x * 64;

    ull acc2[4][4];
#pragma unroll
    for (int p = 0; p < 4; p++)
#pragma unroll
        for (int j = 0; j < 4; j++) acc2[p][j] = 0ull;

    int arow = tid >> 1;
    int ak   = (tid & 1) * 4;
    int brow = tid >> 2;
    int bk   = (tid & 3) * 2;

    const float* Arow = A + (size_t)(m0 + arow) * K;
    const float* Wrow = W + (size_t)(n0 + brow) * K;

    for (int k0 = 0; k0 < K; k0 += 8) {
#pragma unroll
        for (int j = 0; j < 4; j++) {
            int k = k0 + ak + j;
            As[ak + j][arow] = (k < K) ? Arow[k] : 0.f;
        }
#pragma unroll
        for (int j = 0; j < 2; j++) {
            int k = k0 + bk + j;
            Bs[bk + j][brow] = (k < K) ? Wrow[k] : 0.f;
        }
        __syncthreads();
#pragma unroll
        for (int kk = 0; kk < 8; kk++) {
            const ulonglong2* ap = (const ulonglong2*)&As[kk][ty * 8];
            ulonglong2 apA = ap[0], apB = ap[1];
            ull am2[4] = {apA.x, apA.y, apB.x, apB.y};
            float4 bv = *(const float4*)&Bs[kk][tx * 4];
            ull bs2[4];
            SPLAT2(bs2[0], bv.x); SPLAT2(bs2[1], bv.y);
            SPLAT2(bs2[2], bv.z); SPLAT2(bs2[3], bv.w);
#pragma unroll
            for (int p = 0; p < 4; p++)
#pragma unroll
                for (int j = 0; j < 4; j++)
                    FFMA2(acc2[p][j], am2[p], bs2[j]);
        }
        __syncthreads();
    }

    float4 bb = *(const float4*)&bias[n0 + tx * 4];
    float bn[4] = {bb.x, bb.y, bb.z, bb.w};
#pragma unroll
    for (int i = 0; i < 8; i++) {
        int m = m0 + ty * 8 + i;
        float4 v;
        float2 f0 = *((float2*)&acc2[i >> 1][0]);
        float2 f1 = *((float2*)&acc2[i >> 1][1]);
        float2 f2 = *((float2*)&acc2[i >> 1][2]);
        float2 f3 = *((float2*)&acc2[i >> 1][3]);
        v.x = ((i & 1) ? f0.y : f0.x) + bn[0];
        v.y = ((i & 1) ? f1.y : f1.x) + bn[1];
        v.z = ((i & 1) ? f2.y : f2.x) + bn[2];
        v.w = ((i & 1) ? f3.y : f3.x) + bn[3];
        *(float4*)&C[(size_t)m * N + n0 + tx * 4] = v;
    }
}

// ---------------- batch-partitioned bidirectional LSTM layer ----------------
__global__ __launch_bounds__(LTHREADS, 1)
void lstm_layer_kernel(const float* __restrict__ G, const float* __restrict__ Whh,
                       float* __restrict__ Ht, float* __restrict__ Hr,
                       unsigned* cnt) {
    extern __shared__ __align__(16) float smem[];

    int tid = threadIdx.x;
    int cid = blockIdx.x >> 3;
    int rg  = blockIdx.x & 7;
    int dir = cid & 1;
    int b8  = cid >> 1;
    unsigned* mycnt = cnt + (dir * 8 + b8) * CSTRIDE;

    // ---- preload U slice: local row r = g*25+jj -> Whh[dir][g*200+rg*25+jj][:] ----
    const float* Ud = Whh + (size_t)dir * 800 * 200;
    for (int idx = tid; idx < 100 * 200; idx += LTHREADS) {
        int r = idx / 200, k = idx - r * 200;
        int g = r / 25, jj = r - g * 25;
        smem[OFF_U + 2 * ub64(r) + k] = Ud[(size_t)(g * 200 + rg * 25 + jj) * 200 + k];
    }
    for (int idx = tid; idx < H_FLOATS; idx += LTHREADS)
        smem[OFF_H + idx] = 0.f;   // step-0 h = 0
    __syncthreads();

    // ---- matvec decode: kq = tid>>6 (k quarter), rp = tid&63 (<50 active) ----
    int kq = tid >> 6;
    int rp = tid & 63;
    bool mactive = rp < 50;
    int r0 = 2 * rp, r1 = r0 + 1;
    const ull* base = (const ull*)smem;
    const ull* pu0 = base + ub64(r0) + kq * 25;
    const ull* pu1 = base + ub64(r1) + kq * 25;
    const ull* hb  = base + (OFF_H / 2) + kq * 25;   // + bl*101

    // ---- epilogue decode (tid < 100) ----
    int ejj = tid >> 2;          // 0..24
    int ebl = tid & 3;           // 0..3
    int jloc = rg * 25 + ejj;    // column within direction
    int gb   = b8 * 4 + ebl;     // global batch
    float creg = 0.f;
    const float* Gbase = G + (size_t)gb * GN + dir * 800 + jloc;

    // G prefetch for step 0
    float gc[4] = {0.f, 0.f, 0.f, 0.f};
    if (tid < 100) {
        int t0 = dir ? (SEQ - 1) : 0;
        const float* Gp = Gbase + (size_t)t0 * (32 * GN);
        gc[0] = __ldg(Gp);       gc[1] = __ldg(Gp + 200);
        gc[2] = __ldg(Gp + 400); gc[3] = __ldg(Gp + 600);
    }

    for (int step = 0; step < SEQ; step++) {
        int t = dir ? (SEQ - 1 - step) : step;

        // ---- exchange-in: wait for group, load h block, transpose to smem ----
        if (step > 0) {
            if (tid == 0) {
                unsigned target = 8u * (unsigned)step;
                unsigned v;
                do {
                    asm volatile("ld.global.acquire.gpu.u32 %0, [%1];"
                                 : "=r"(v) : "l"(mycnt) : "memory");
                } while (v < target);
            }
            __syncthreads();
            int tp = dir ? (t + 1) : (t - 1);
            const float* Hp = Ht + ((size_t)tp * 16 + dir * 8 + b8) * 800;
            if (tid < 200) {
                float4 v = __ldcg((const float4*)(Hp + tid * 4));
                smem[OFF_H + 0 * 202 + tid] = v.x;
                smem[OFF_H + 1 * 202 + tid] = v.y;
                smem[OFF_H + 2 * 202 + tid] = v.z;
                smem[OFF_H + 3 * 202 + tid] = v.w;
            }
            __syncthreads();
        }

        // ---- matvec: 2 rows x 4 batches over k-quarter (25 u64) ----
        if (mactive) {
            const ull* ph0 = hb;
            const ull* ph1 = hb + 101;
            const ull* ph2 = hb + 202;
            const ull* ph3 = hb + 303;
            ull a0[4], a1[4];
#pragma unroll
            for (int b = 0; b < 4; b++) { a0[b] = 0ull; a1[b] = 0ull; }
#pragma unroll
            for (int kk = 0; kk < 25; kk++) {
                ull u0 = pu0[kk], u1 = pu1[kk];
                ull h0 = ph0[kk], h1 = ph1[kk], h2 = ph2[kk], h3 = ph3[kk];
                FFMA2(a0[0], u0, h0); FFMA2(a0[1], u0, h1);
                FFMA2(a0[2], u0, h2); FFMA2(a0[3], u0, h3);
                FFMA2(a1[0], u1, h0); FFMA2(a1[1], u1, h1);
                FFMA2(a1[2], u1, h2); FFMA2(a1[3], u1, h3);
            }
#pragma unroll
            for (int b = 0; b < 4; b++) {
                float2 f;
                f = *(float2*)&a0[b];
                smem[OFF_P + kq * 500 + r0 * 5 + b] = f.x + f.y;
                f = *(float2*)&a1[b];
                smem[OFF_P + kq * 500 + r1 * 5 + b] = f.x + f.y;
            }
        }
        __syncthreads();

        // ---- epilogue: reduce partials, gates, publish ----
        if (tid < 100) {
            float y[4];
#pragma unroll
            for (int g = 0; g < 4; g++) {
                int r = g * 25 + ejj;
                y[g] = smem[OFF_P + 0 * 500 + r * 5 + ebl]
                     + smem[OFF_P + 1 * 500 + r * 5 + ebl]
                     + smem[OFF_P + 2 * 500 + r * 5 + ebl]
                     + smem[OFF_P + 3 * 500 + r * 5 + ebl];
            }
            float yi = y[0] + gc[0];
            float yf = y[1] + gc[1];
            float yg = y[2] + gc[2];
            float yo = y[3] + gc[3];
            float c = fsig(yf) * creg + fsig(yi) * ftanh(yg);
            float hn = fsig(yo) * ftanh(c);
            creg = c;
            // exchange-out: contiguous 400B block per CTA
            Ht[((size_t)t * 16 + dir * 8 + b8) * 800 + jloc * 4 + ebl] = hn;
            // row-major output for GEMM / head
            Hr[(size_t)(t * 32 + gb) * 400 + dir * 200 + jloc] = hn;
            // G prefetch for next step (hides under barrier + h-load)
            if (step + 1 < SEQ) {
                int tn = dir ? (t - 1) : (t + 1);
                const float* Gp = Gbase + (size_t)tn * (32 * GN);
                gc[0] = __ldg(Gp);       gc[1] = __ldg(Gp + 200);
                gc[2] = __ldg(Gp + 400); gc[3] = __ldg(Gp + 600);
            }
        }
        __syncthreads();   // all Ht stores done before release

        if (step < SEQ - 1 && tid == 0) {
            asm volatile("red.release.gpu.global.add.u32 [%0], 1;"
                         :: "l"(mycnt) : "memory");
        }
    }
}

// ---------------- output head ----------------
__global__ void out_kernel(const float* __restrict__ ow, const float* __restrict__ ob,
                           float* __restrict__ out) {
    int row  = blockIdx.x;           // = s*32 + b
    int warp = threadIdx.x >> 5;     // 0..16 = tag
    int lane = threadIdx.x & 31;
    const float* h    = d_H1r + (size_t)row * 400;
    const float* wrow = ow + warp * 400;
    float sum = 0.f;
#pragma unroll
    for (int k = lane; k < 400; k += 32) sum = fmaf(h[k], wrow[k], sum);
#pragma unroll
    for (int o = 16; o; o >>= 1) sum += __shfl_down_sync(0xffffffffu, sum, o);
    if (lane == 0) {
        int s = row >> 5, b = row & 31;
        out[((size_t)b * SEQ + s) * NTAG + warp] = fsig(sum + ob[warp]);
    }
}

// ---------------- launch ----------------
extern "C" void kernel_launch(void* const* d_in, const int* in_sizes, int n_in,
                              void* d_out, int out_size) {
    const int*   words = (const int*)  d_in[0];
    const float* emb   = (const float*)d_in[3];
    const float* Wih0  = (const float*)d_in[7];
    const float* Whh0  = (const float*)d_in[8];
    const float* b0    = (const float*)d_in[9];
    const float* Wih1  = (const float*)d_in[10];
    const float* Whh1  = (const float*)d_in[11];
    const float* b1    = (const float*)d_in[12];
    const float* ow    = (const float*)d_in[13];
    const float* ob    = (const float*)d_in[14];
    float* out = (float*)d_out;

    float *pX0, *pG0, *pG1, *pH0r, *pH1r, *pHt;
    unsigned* pcnt;
    cudaGetSymbolAddress((void**)&pX0, d_X0);
    cudaGetSymbolAddress((void**)&pG0, d_G0);
    cudaGetSymbolAddress((void**)&pG1, d_G1);
    cudaGetSymbolAddress((void**)&pH0r, d_H0r);
    cudaGetSymbolAddress((void**)&pH1r, d_H1r);
    cudaGetSymbolAddress((void**)&pHt, d_Ht);
    cudaGetSymbolAddress((void**)&pcnt, g_cnt);

    static int smem_set = 0;
    if (!smem_set) {
        cudaFuncSetAttribute(lstm_layer_kernel,
                             cudaFuncAttributeMaxDynamicSharedMemorySize, SMEM_BYTES);
        smem_set = 1;
    }

    reset_cnt_kernel<<<2, 512>>>();

    gather_kernel<<<(ROWS * EDIM + 255) / 256, 256>>>(words, emb);

    dim3 gdim0(GN / 64, ROWS / 128);
    sgemm_bias_kernel<<<gdim0, 256>>>(pX0, Wih0, b0, pG0, ROWS, GN, EDIM);

    lstm_layer_kernel<<<128, LTHREADS, SMEM_BYTES>>>(pG0, Whh0, pHt, pH0r,
                                                     pcnt + 0 * 16 * CSTRIDE);

    sgemm_bias_kernel<<<gdim0, 256>>>(pH0r, Wih1, b1, pG1, ROWS, GN, 400);

    lstm_layer_kernel<<<128, LTHREADS, SMEM_BYTES>>>(pG1, Whh1, pHt, pH1r,
                                                     pcnt + 1 * 16 * CSTRIDE);

    out_kernel<<<ROWS, NTAG * 32>>>(ow, ob, out);
}